// round 1
// baseline (speedup 1.0000x reference)
#include <cuda_runtime.h>
#include <cuda_bf16.h>

// Problem constants
#define N_TOK   8192     // B*T = 4*2048
#define DIN     4096
#define DOUT    4096
#define S_RANK  256
#define S_CAT   512      // both branches concatenated

// Scratch (device globals; no allocation allowed)
__device__ float g_B[DIN * S_CAT];    // Bcat[i, s]   (row-major, K-major for GEMM1)
__device__ float g_W[S_CAT * DOUT];   // Wcat[s, j]
__device__ float g_H[N_TOK * S_CAT];  // H[n, s]

__device__ __forceinline__ float sgn(float v) {
    return (v > 0.0f) ? 1.0f : ((v < 0.0f) ? -1.0f : 0.0f);
}

// ---------------------------------------------------------------------------
// Prep: fold all per-axis scales into the sign matrices.
// ---------------------------------------------------------------------------
__global__ void build_B_kernel(const float* __restrict__ V,  const float* __restrict__ VR,
                               const float* __restrict__ v1, const float* __restrict__ v2,
                               const float* __restrict__ u2,
                               const float* __restrict__ v1R, const float* __restrict__ v2R,
                               const float* __restrict__ u2R) {
    int idx = blockIdx.x * blockDim.x + threadIdx.x;
    if (idx >= DIN * S_CAT) return;
    int i = idx / S_CAT;
    int s = idx % S_CAT;
    float val;
    if (s < S_RANK) {
        val = sgn(V[s * DIN + i]) * v2[i] * v1[s] * u2[s];
    } else {
        int s2 = s - S_RANK;
        val = sgn(VR[s2 * DIN + i]) * v2R[i] * v1R[s2] * u2R[s2];
    }
    g_B[idx] = val;
}

__global__ void build_W_kernel(const float* __restrict__ U,  const float* __restrict__ UR,
                               const float* __restrict__ u1, const float* __restrict__ u1R) {
    int idx = blockIdx.x * blockDim.x + threadIdx.x;
    if (idx >= S_CAT * DOUT) return;
    int s = idx / DOUT;
    int j = idx % DOUT;
    float val;
    if (s < S_RANK) {
        val = sgn(U[j * S_RANK + s]) * u1[j];
    } else {
        val = sgn(UR[j * S_RANK + (s - S_RANK)]) * u1R[j];
    }
    g_W[idx] = val;
}

// ---------------------------------------------------------------------------
// SGEMM: C[M,N] = A[M,K] @ B[K,N] (+ bias per column), fp32.
// 128x128 block tile, BK=16, 8x8 per-thread tile, 256 threads.
// ---------------------------------------------------------------------------
template <int M, int N, int K, bool HAS_BIAS>
__device__ __forceinline__ void sgemm_body(const float* __restrict__ A,
                                           const float* __restrict__ B,
                                           float* __restrict__ C,
                                           const float* __restrict__ bias) {
    constexpr int BM = 128, BN = 128, BK = 16, TM = 8, TN = 8;
    __shared__ float As[BK][BM];      // stored transposed: As[k][m]
    __shared__ float Bs[BK][BN];

    const int tid  = threadIdx.x;
    const int cRow = blockIdx.y;
    const int cCol = blockIdx.x;

    const int threadCol = tid % (BN / TN);   // 0..15
    const int threadRow = tid / (BN / TN);   // 0..15

    const float* Ab = A + (size_t)cRow * BM * K;
    const float* Bb = B + (size_t)cCol * BN;

    // A loads: float4 per thread; rows tid/4 (+64), col4 tid%4
    const int aRow  = tid / (BK / 4);   // 0..63
    const int aCol4 = tid % (BK / 4);   // 0..3
    // B loads: rows tid/32 (+8 stride), col4 tid%32
    const int bRow  = tid / (BN / 4);   // 0..7
    const int bCol4 = tid % (BN / 4);   // 0..31

    float acc[TM][TN] = {};
    float regM[TM], regN[TN];

    for (int k0 = 0; k0 < K; k0 += BK) {
        // Load A tile (transposed into SMEM)
        #pragma unroll
        for (int r = 0; r < BM; r += 64) {
            float4 v = *(const float4*)&Ab[(size_t)(aRow + r) * K + k0 + aCol4 * 4];
            As[aCol4 * 4 + 0][aRow + r] = v.x;
            As[aCol4 * 4 + 1][aRow + r] = v.y;
            As[aCol4 * 4 + 2][aRow + r] = v.z;
            As[aCol4 * 4 + 3][aRow + r] = v.w;
        }
        // Load B tile
        #pragma unroll
        for (int r = 0; r < BK; r += 8) {
            float4 v = *(const float4*)&Bb[(size_t)(k0 + bRow + r) * N + bCol4 * 4];
            *(float4*)&Bs[bRow + r][bCol4 * 4] = v;
        }
        __syncthreads();

        #pragma unroll
        for (int k = 0; k < BK; ++k) {
            *(float4*)&regM[0] = *(const float4*)&As[k][threadRow * TM];
            *(float4*)&regM[4] = *(const float4*)&As[k][threadRow * TM + 4];
            *(float4*)&regN[0] = *(const float4*)&Bs[k][threadCol * TN];
            *(float4*)&regN[4] = *(const float4*)&Bs[k][threadCol * TN + 4];
            #pragma unroll
            for (int i = 0; i < TM; ++i)
                #pragma unroll
                for (int j = 0; j < TN; ++j)
                    acc[i][j] += regM[i] * regN[j];
        }
        __syncthreads();
    }

    // Epilogue
    #pragma unroll
    for (int i = 0; i < TM; ++i) {
        const size_t row = (size_t)cRow * BM + threadRow * TM + i;
        #pragma unroll
        for (int j = 0; j < TN; j += 4) {
            const int col = cCol * BN + threadCol * TN + j;
            float4 v;
            v.x = acc[i][j + 0];
            v.y = acc[i][j + 1];
            v.z = acc[i][j + 2];
            v.w = acc[i][j + 3];
            if (HAS_BIAS) {
                v.x += bias[col + 0];
                v.y += bias[col + 1];
                v.z += bias[col + 2];
                v.w += bias[col + 3];
            }
            *(float4*)&C[row * N + col] = v;
        }
    }
}

__global__ __launch_bounds__(256, 1) void gemm1_kernel(const float* __restrict__ x) {
    // H[8192, 512] = x[8192, 4096] @ Bcat[4096, 512]
    sgemm_body<N_TOK, S_CAT, DIN, false>(x, g_B, g_H, nullptr);
}

__global__ __launch_bounds__(256, 1) void gemm2_kernel(float* __restrict__ out,
                                                       const float* __restrict__ bias) {
    // y[8192, 4096] = H[8192, 512] @ Wcat[512, 4096] + bias
    sgemm_body<N_TOK, DOUT, S_CAT, true>(g_H, g_W, out, bias);
}

// ---------------------------------------------------------------------------
// Launch
// ---------------------------------------------------------------------------
extern "C" void kernel_launch(void* const* d_in, const int* in_sizes, int n_in,
                              void* d_out, int out_size) {
    const float* x    = (const float*)d_in[0];
    const float* V    = (const float*)d_in[1];
    const float* U    = (const float*)d_in[2];
    const float* v1   = (const float*)d_in[3];
    const float* v2   = (const float*)d_in[4];
    const float* u1   = (const float*)d_in[5];
    const float* u2   = (const float*)d_in[6];
    const float* V_R  = (const float*)d_in[7];
    const float* U_R  = (const float*)d_in[8];
    const float* v1_R = (const float*)d_in[9];
    const float* v2_R = (const float*)d_in[10];
    const float* u1_R = (const float*)d_in[11];
    const float* u2_R = (const float*)d_in[12];
    const float* bias = (const float*)d_in[13];
    float* out = (float*)d_out;

    // Prep: fold scales into sign matrices
    {
        int total = DIN * S_CAT;
        build_B_kernel<<<(total + 255) / 256, 256>>>(V, V_R, v1, v2, u2, v1_R, v2_R, u2_R);
    }
    {
        int total = S_CAT * DOUT;
        build_W_kernel<<<(total + 255) / 256, 256>>>(U, U_R, u1, u1_R);
    }

    // GEMM1: H = x @ Bcat   grid (N/128, M/128) = (4, 64)
    gemm1_kernel<<<dim3(S_CAT / 128, N_TOK / 128), 256>>>(x);

    // GEMM2: y = H @ Wcat + bias   grid (32, 64)
    gemm2_kernel<<<dim3(DOUT / 128, N_TOK / 128), 256>>>(out, bias);
}

// round 3
// speedup vs baseline: 5.2149x; 5.2149x over previous
#include <cuda_runtime.h>
#include <cuda_fp16.h>
#include <cstdint>
#include <cstddef>

// ---------------------------------------------------------------------------
// Problem constants
// ---------------------------------------------------------------------------
#define N_TOK   8192
#define DIN     4096
#define DOUT    4096
#define S_RANK  256
#define S_CAT   512

// GEMM tiling
#define BM      128
#define BN      128
#define BK      64          // 64 fp16 = 128 bytes per row -> SW128 swizzle
#define STAGES  3
#define THREADS 256
#define STAGE_A_BYTES (BM * 128)              // 16384
#define STAGE_B_BYTES (BN * 128)              // 16384
#define STAGE_BYTES   (STAGE_A_BYTES + STAGE_B_BYTES)       // 32768
#define SMEM_DYN_BYTES (STAGES * STAGE_BYTES)               // 98304

// ---------------------------------------------------------------------------
// Scratch (device globals; no runtime allocation)
// ---------------------------------------------------------------------------
__device__ __half g_xh[(size_t)N_TOK * DIN];     // fp16(x)                64 MB
__device__ __half g_B1[(size_t)S_CAT * DIN];     // sign(V)*v2*v1*u2        4 MB
__device__ __half g_B2[(size_t)DOUT * S_CAT];    // sign(U)*u1              4 MB
__device__ __half g_H [(size_t)N_TOK * S_CAT];   // H fp16                  8 MB

// ---------------------------------------------------------------------------
// Helpers
// ---------------------------------------------------------------------------
__device__ __forceinline__ uint32_t smem_u32(const void* p) {
    uint32_t a;
    asm("{ .reg .u64 t; cvta.to.shared.u64 t, %1; cvt.u32.u64 %0, t; }" : "=r"(a) : "l"(p));
    return a;
}

#define SWZ(o) ((o) ^ (((o) >> 3) & 0x70))

#define CP_ASYNC16(s, g) \
    asm volatile("cp.async.cg.shared.global [%0], [%1], 16;" :: "r"(s), "l"(g))
#define CP_COMMIT() asm volatile("cp.async.commit_group;")
#define CP_WAIT(n)  asm volatile("cp.async.wait_group %0;" :: "n"(n) : "memory")

#define LDMATRIX_X4(r0, r1, r2, r3, addr)                                     \
    asm volatile("ldmatrix.sync.aligned.m8n8.x4.shared.b16 {%0,%1,%2,%3}, [%4];" \
        : "=r"(r0), "=r"(r1), "=r"(r2), "=r"(r3) : "r"(addr))

#define MMA_16816(d, a, b0, b1)                                               \
    asm volatile("mma.sync.aligned.m16n8k16.row.col.f32.f16.f16.f32 "         \
        "{%0,%1,%2,%3}, {%4,%5,%6,%7}, {%8,%9}, {%0,%1,%2,%3};"               \
        : "+f"((d)[0]), "+f"((d)[1]), "+f"((d)[2]), "+f"((d)[3])              \
        : "r"((a)[0]), "r"((a)[1]), "r"((a)[2]), "r"((a)[3]), "r"(b0), "r"(b1))

__device__ __forceinline__ float sgn(float v) {
    return (v > 0.0f) ? 1.0f : ((v < 0.0f) ? -1.0f : 0.0f);
}

// ---------------------------------------------------------------------------
// Prep kernels
// ---------------------------------------------------------------------------
__global__ void prep_x_kernel(const float4* __restrict__ x) {
    size_t i = (size_t)blockIdx.x * blockDim.x + threadIdx.x;   // 8388608 float4
    float4 v = x[i];
    __half2* o = (__half2*)&g_xh[4 * i];
    o[0] = __floats2half2_rn(v.x, v.y);
    o[1] = __floats2half2_rn(v.z, v.w);
}

// B1[s][i] = sign(Vcat[s][i]) * v2cat[i] * v1cat[s] * u2cat[s]   (all scales folded)
__global__ void prep_B1_kernel(const float* __restrict__ V,   const float* __restrict__ VR,
                               const float* __restrict__ v2,  const float* __restrict__ v2R,
                               const float* __restrict__ v1,  const float* __restrict__ v1R,
                               const float* __restrict__ u2,  const float* __restrict__ u2R) {
    int idx = blockIdx.x * blockDim.x + threadIdx.x;   // S_CAT*DIN
    int s = idx >> 12;
    int i = idx & 4095;
    float val;
    if (s < S_RANK) val = sgn(V [(size_t)s * DIN + i]) * v2[i] * v1[s] * u2[s];
    else {
        int s2 = s - S_RANK;
        val = sgn(VR[(size_t)s2 * DIN + i]) * v2R[i] * v1R[s2] * u2R[s2];
    }
    g_B1[idx] = __float2half(val);
}

__global__ void prep_B2_kernel(const float* __restrict__ U,  const float* __restrict__ UR,
                               const float* __restrict__ u1, const float* __restrict__ u1R) {
    int idx = blockIdx.x * blockDim.x + threadIdx.x;   // DOUT*S_CAT
    int j = idx >> 9;
    int s = idx & 511;
    float val;
    if (s < S_RANK) val = sgn(U [(size_t)j * S_RANK + s]) * u1[j];
    else            val = sgn(UR[(size_t)j * S_RANK + (s - S_RANK)]) * u1R[j];
    g_B2[idx] = __float2half(val);
}

// ---------------------------------------------------------------------------
// Tile loader: stage `it` -> buffer it%STAGES (A: BM rows, B: BN rows, 128B each)
// ---------------------------------------------------------------------------
template <int K>
__device__ __forceinline__ void load_stage(const __half* __restrict__ A,
                                           const __half* __restrict__ B,
                                           uint32_t sm_tiles, int it, int m0, int n0, int tid) {
    const uint32_t sbase = sm_tiles + (it % STAGES) * STAGE_BYTES;
    const int k0 = it * BK;
    #pragma unroll
    for (int u = 0; u < 8; ++u) {
        int q = tid + u * THREADS;            // 0..2047
        if (q < 1024) {                       // A: 128 rows x 8 16B-chunks
            int row = q >> 3, c = q & 7;
            const __half* g = A + (size_t)(m0 + row) * K + k0 + c * 8;
            CP_ASYNC16(sbase + SWZ((uint32_t)(row * 128 + c * 16)), g);
        } else {                              // B: 128 rows x 8 chunks
            int qb = q - 1024;
            int row = qb >> 3, c = qb & 7;
            const __half* g = B + (size_t)(n0 + row) * K + k0 + c * 8;
            CP_ASYNC16(sbase + STAGE_A_BYTES + SWZ((uint32_t)(row * 128 + c * 16)), g);
        }
    }
}

// ---------------------------------------------------------------------------
// HMMA GEMM: C[M,N] = A[M,K] @ B[N,K]^T   (fp16 in, fp32 accum)
// EPI==1: store fp16 to g_H.  EPI==2: add bias, store fp32 to out.
// ---------------------------------------------------------------------------
template <int K, int EPI>
__global__ __launch_bounds__(THREADS) void gemm_kernel(float* __restrict__ out,
                                                       const float* __restrict__ bias) {
    extern __shared__ char smem_raw[];
    const uint32_t sm_tiles = smem_u32(smem_raw);
    const int tid  = threadIdx.x;
    const int wid  = tid >> 5;
    const int lane = tid & 31;
    const int m0 = blockIdx.y * BM;
    const int n0 = blockIdx.x * BN;
    constexpr int NIT = K / BK;

    const __half* A = (EPI == 1) ? g_xh : g_H;
    const __half* B = (EPI == 1) ? g_B1 : g_B2;

    // Warp grid: 2 (M) x 4 (N); warp tile 64x32
    const int wm = wid >> 2;
    const int wn = wid & 3;

    // ldmatrix per-lane addressing
    const int ldRow = lane & 15;         // row within 16-row block
    const int ldSel = lane >> 4;         // 0/1 -> +16 bytes (8 halfs)
    const uint32_t aOffBase = (uint32_t)((wm * 64 + ldRow) * 128 + ldSel * 16);
    const uint32_t bOffBase = (uint32_t)((wn * 32 + ldRow) * 128 + ldSel * 16);

    float acc[4][4][4] = {};   // [m16 tile][n8 tile][frag]

    // Prologue
    #pragma unroll
    for (int s = 0; s < STAGES - 1; ++s) {
        load_stage<K>(A, B, sm_tiles, s, m0, n0, tid);
        CP_COMMIT();
    }

    #pragma unroll 1
    for (int it = 0; it < NIT; ++it) {
        CP_WAIT(STAGES - 2);
        __syncthreads();

        const uint32_t sA = sm_tiles + (it % STAGES) * STAGE_BYTES;
        const uint32_t sB = sA + STAGE_A_BYTES;

        #pragma unroll
        for (int ks = 0; ks < BK / 16; ++ks) {
            uint32_t af[4][4], bf[2][4];
            #pragma unroll
            for (int i = 0; i < 4; ++i)
                LDMATRIX_X4(af[i][0], af[i][1], af[i][2], af[i][3],
                            sA + SWZ(aOffBase + (uint32_t)(i * 16 * 128 + ks * 32)));
            #pragma unroll
            for (int jj = 0; jj < 2; ++jj)
                LDMATRIX_X4(bf[jj][0], bf[jj][1], bf[jj][2], bf[jj][3],
                            sB + SWZ(bOffBase + (uint32_t)(jj * 16 * 128 + ks * 32)));
            #pragma unroll
            for (int i = 0; i < 4; ++i)
                #pragma unroll
                for (int j = 0; j < 4; ++j) {
                    // n8 tile j: jj=j>>1, half=(j&1): regs {r[half], r[half+2]}
                    MMA_16816(acc[i][j], af[i], bf[j >> 1][(j & 1)], bf[j >> 1][(j & 1) + 2]);
                }
        }
        __syncthreads();

        if (it + STAGES - 1 < NIT)
            load_stage<K>(A, B, sm_tiles, it + STAGES - 1, m0, n0, tid);
        CP_COMMIT();
    }

    // Epilogue: frag (c0,c1)@(r, c..c+1), (c2,c3)@(r+8, c..c+1)
    const int rBase = m0 + wm * 64 + (lane >> 2);
    const int cBase = n0 + wn * 32 + (lane & 3) * 2;
    #pragma unroll
    for (int i = 0; i < 4; ++i) {
        const int r = rBase + i * 16;
        #pragma unroll
        for (int j = 0; j < 4; ++j) {
            const int c = cBase + j * 8;
            if (EPI == 1) {
                *(__half2*)&g_H[(size_t)r * S_CAT + c] =
                    __floats2half2_rn(acc[i][j][0], acc[i][j][1]);
                *(__half2*)&g_H[(size_t)(r + 8) * S_CAT + c] =
                    __floats2half2_rn(acc[i][j][2], acc[i][j][3]);
            } else {
                const float b0 = bias[c], b1 = bias[c + 1];
                float2 v0 = make_float2(acc[i][j][0] + b0, acc[i][j][1] + b1);
                float2 v1 = make_float2(acc[i][j][2] + b0, acc[i][j][3] + b1);
                *(float2*)&out[(size_t)r * DOUT + c] = v0;
                *(float2*)&out[(size_t)(r + 8) * DOUT + c] = v1;
            }
        }
    }
}

// ---------------------------------------------------------------------------
// Launch
// ---------------------------------------------------------------------------
extern "C" void kernel_launch(void* const* d_in, const int* in_sizes, int n_in,
                              void* d_out, int out_size) {
    const float* x    = (const float*)d_in[0];
    const float* V    = (const float*)d_in[1];
    const float* U    = (const float*)d_in[2];
    const float* v1   = (const float*)d_in[3];
    const float* v2   = (const float*)d_in[4];
    const float* u1   = (const float*)d_in[5];
    const float* u2   = (const float*)d_in[6];
    const float* V_R  = (const float*)d_in[7];
    const float* U_R  = (const float*)d_in[8];
    const float* v1_R = (const float*)d_in[9];
    const float* v2_R = (const float*)d_in[10];
    const float* u1_R = (const float*)d_in[11];
    const float* u2_R = (const float*)d_in[12];
    const float* bias = (const float*)d_in[13];
    float* out = (float*)d_out;

    cudaFuncSetAttribute(gemm_kernel<DIN, 1>,
                         cudaFuncAttributeMaxDynamicSharedMemorySize, SMEM_DYN_BYTES);
    cudaFuncSetAttribute(gemm_kernel<S_CAT, 2>,
                         cudaFuncAttributeMaxDynamicSharedMemorySize, SMEM_DYN_BYTES);

    // Prep
    prep_x_kernel<<<(int)((size_t)N_TOK * DIN / 4 / 256), 256>>>((const float4*)x);
    prep_B1_kernel<<<(S_CAT * DIN) / 256, 256>>>(V, V_R, v2, v2_R, v1, v1_R, u2, u2_R);
    prep_B2_kernel<<<(DOUT * S_CAT) / 256, 256>>>(U, U_R, u1, u1_R);

    // GEMM1: H = fp16(x) @ B1^T   grid (512/128, 8192/128) = (4, 64)
    gemm_kernel<DIN, 1><<<dim3(S_CAT / BN, N_TOK / BM), THREADS, SMEM_DYN_BYTES>>>(nullptr, nullptr);

    // GEMM2: y = H @ B2^T + bias  grid (32, 64)
    gemm_kernel<S_CAT, 2><<<dim3(DOUT / BN, N_TOK / BM), THREADS, SMEM_DYN_BYTES>>>(out, bias);
}

// round 4
// speedup vs baseline: 5.6727x; 1.0878x over previous
#include <cuda_runtime.h>
#include <cuda_fp16.h>
#include <cstdint>
#include <cstddef>

// ---------------------------------------------------------------------------
// Problem constants
// ---------------------------------------------------------------------------
#define N_TOK   8192
#define DIN     4096
#define DOUT    4096
#define S_RANK  256
#define S_CAT   512

// GEMM tiling
#define BM      128
#define BN      256
#define BK      64          // 64 fp16 = 128 bytes per row -> SW128 swizzle
#define STAGES  3
#define THREADS 256
#define STAGE_A_BYTES (BM * 128)              // 16384
#define STAGE_B_BYTES (BN * 128)              // 32768
#define STAGE_BYTES   (STAGE_A_BYTES + STAGE_B_BYTES)       // 49152
#define SMEM_DYN_BYTES (STAGES * STAGE_BYTES)               // 147456

// ---------------------------------------------------------------------------
// Scratch (device globals; no runtime allocation)
// ---------------------------------------------------------------------------
__device__ __half g_xh[(size_t)N_TOK * DIN];     // fp16(x)                64 MB
__device__ __half g_B1[(size_t)S_CAT * DIN];     // sign(V)*v2*v1*u2        4 MB
__device__ __half g_B2[(size_t)DOUT * S_CAT];    // sign(U)*u1              4 MB
__device__ __half g_H [(size_t)N_TOK * S_CAT];   // H fp16                  8 MB

// ---------------------------------------------------------------------------
// Helpers
// ---------------------------------------------------------------------------
__device__ __forceinline__ uint32_t smem_u32(const void* p) {
    uint32_t a;
    asm("{ .reg .u64 t; cvta.to.shared.u64 t, %1; cvt.u32.u64 %0, t; }" : "=r"(a) : "l"(p));
    return a;
}

#define SWZ(o) ((o) ^ (((o) >> 3) & 0x70))

#define CP_ASYNC16(s, g) \
    asm volatile("cp.async.cg.shared.global [%0], [%1], 16;" :: "r"(s), "l"(g))
#define CP_COMMIT() asm volatile("cp.async.commit_group;")
#define CP_WAIT(n)  asm volatile("cp.async.wait_group %0;" :: "n"(n) : "memory")

#define LDMATRIX_X4(r0, r1, r2, r3, addr)                                     \
    asm volatile("ldmatrix.sync.aligned.m8n8.x4.shared.b16 {%0,%1,%2,%3}, [%4];" \
        : "=r"(r0), "=r"(r1), "=r"(r2), "=r"(r3) : "r"(addr))

#define MMA_16816(d, a, b0, b1)                                               \
    asm volatile("mma.sync.aligned.m16n8k16.row.col.f32.f16.f16.f32 "         \
        "{%0,%1,%2,%3}, {%4,%5,%6,%7}, {%8,%9}, {%0,%1,%2,%3};"               \
        : "+f"((d)[0]), "+f"((d)[1]), "+f"((d)[2]), "+f"((d)[3])              \
        : "r"((a)[0]), "r"((a)[1]), "r"((a)[2]), "r"((a)[3]), "r"(b0), "r"(b1))

__device__ __forceinline__ float sgn(float v) {
    return (v > 0.0f) ? 1.0f : ((v < 0.0f) ? -1.0f : 0.0f);
}

// ---------------------------------------------------------------------------
// Prep kernels
// ---------------------------------------------------------------------------
__global__ void prep_x_kernel(const float4* __restrict__ x) {
    size_t i = (size_t)blockIdx.x * blockDim.x + threadIdx.x;   // 8388608 float4
    float4 v = x[i];
    __half2* o = (__half2*)&g_xh[4 * i];
    o[0] = __floats2half2_rn(v.x, v.y);
    o[1] = __floats2half2_rn(v.z, v.w);
}

// B1[s][i] = sign(Vcat[s][i]) * v2cat[i] * v1cat[s] * u2cat[s]   (all scales folded)
__global__ void prep_B1_kernel(const float* __restrict__ V,   const float* __restrict__ VR,
                               const float* __restrict__ v2,  const float* __restrict__ v2R,
                               const float* __restrict__ v1,  const float* __restrict__ v1R,
                               const float* __restrict__ u2,  const float* __restrict__ u2R) {
    int idx = blockIdx.x * blockDim.x + threadIdx.x;   // S_CAT*DIN
    int s = idx >> 12;
    int i = idx & 4095;
    float val;
    if (s < S_RANK) val = sgn(V [(size_t)s * DIN + i]) * v2[i] * v1[s] * u2[s];
    else {
        int s2 = s - S_RANK;
        val = sgn(VR[(size_t)s2 * DIN + i]) * v2R[i] * v1R[s2] * u2R[s2];
    }
    g_B1[idx] = __float2half(val);
}

__global__ void prep_B2_kernel(const float* __restrict__ U,  const float* __restrict__ UR,
                               const float* __restrict__ u1, const float* __restrict__ u1R) {
    int idx = blockIdx.x * blockDim.x + threadIdx.x;   // DOUT*S_CAT
    int j = idx >> 9;
    int s = idx & 511;
    float val;
    if (s < S_RANK) val = sgn(U [(size_t)j * S_RANK + s]) * u1[j];
    else            val = sgn(UR[(size_t)j * S_RANK + (s - S_RANK)]) * u1R[j];
    g_B2[idx] = __float2half(val);
}

// ---------------------------------------------------------------------------
// Tile loader: stage `it` -> buffer it%STAGES (A: BM rows, B: BN rows, 128B each)
// ---------------------------------------------------------------------------
template <int K>
__device__ __forceinline__ void load_stage(const __half* __restrict__ A,
                                           const __half* __restrict__ B,
                                           uint32_t sm_tiles, int it, int m0, int n0, int tid) {
    const uint32_t sbase = sm_tiles + (it % STAGES) * STAGE_BYTES;
    const int k0 = it * BK;
    #pragma unroll
    for (int u = 0; u < 12; ++u) {
        int q = tid + u * THREADS;            // 0..3071
        if (q < 1024) {                       // A: 128 rows x 8 16B-chunks
            int row = q >> 3, c = q & 7;
            const __half* g = A + (size_t)(m0 + row) * K + k0 + c * 8;
            CP_ASYNC16(sbase + SWZ((uint32_t)(row * 128 + c * 16)), g);
        } else {                              // B: 256 rows x 8 chunks
            int qb = q - 1024;
            int row = qb >> 3, c = qb & 7;
            const __half* g = B + (size_t)(n0 + row) * K + k0 + c * 8;
            CP_ASYNC16(sbase + STAGE_A_BYTES + SWZ((uint32_t)(row * 128 + c * 16)), g);
        }
    }
}

// ---------------------------------------------------------------------------
// HMMA GEMM: C[M,N] = A[M,K] @ B[N,K]^T   (fp16 in, fp32 accum)
// CTA 128x256, warps 2x4 of 64x64.
// EPI==1: store fp16 to g_H.  EPI==2: add bias, store fp32 to out.
// ---------------------------------------------------------------------------
template <int K, int EPI>
__global__ __launch_bounds__(THREADS, 1) void gemm_kernel(float* __restrict__ out,
                                                          const float* __restrict__ bias) {
    extern __shared__ char smem_raw[];
    const uint32_t sm_tiles = smem_u32(smem_raw);
    const int tid  = threadIdx.x;
    const int wid  = tid >> 5;
    const int lane = tid & 31;
    const int m0 = blockIdx.y * BM;
    const int n0 = blockIdx.x * BN;
    constexpr int NIT = K / BK;

    const __half* A = (EPI == 1) ? g_xh : g_H;
    const __half* B = (EPI == 1) ? g_B1 : g_B2;

    // Warp grid: 2 (M) x 4 (N); warp tile 64x64
    const int wm = wid >> 2;
    const int wn = wid & 3;

    // ldmatrix per-lane addressing
    const int ldRow = lane & 15;         // row within 16-row block
    const int ldSel = lane >> 4;         // 0/1 -> +16 bytes
    const uint32_t aOffBase = (uint32_t)((wm * 64 + ldRow) * 128 + ldSel * 16);
    const uint32_t bOffBase = (uint32_t)((wn * 64 + ldRow) * 128 + ldSel * 16);

    float acc[4][8][4] = {};   // [m16 tile][n8 tile][frag]

    // Prologue
    #pragma unroll
    for (int s = 0; s < STAGES - 1; ++s) {
        load_stage<K>(A, B, sm_tiles, s, m0, n0, tid);
        CP_COMMIT();
    }

    #pragma unroll 1
    for (int it = 0; it < NIT; ++it) {
        CP_WAIT(STAGES - 2);
        __syncthreads();       // stage `it` fully resident; prior MMAs done

        // Prefetch stage it+2 NOW (overlaps with MMA below). Buffer
        // (it+2)%STAGES was last read in iter it-1, which completed before
        // the barrier above.
        if (it + STAGES - 1 < NIT)
            load_stage<K>(A, B, sm_tiles, it + STAGES - 1, m0, n0, tid);
        CP_COMMIT();

        const uint32_t sA = sm_tiles + (it % STAGES) * STAGE_BYTES;
        const uint32_t sB = sA + STAGE_A_BYTES;

        #pragma unroll
        for (int ks = 0; ks < BK / 16; ++ks) {
            uint32_t af[4][4], bf[4][4];
            #pragma unroll
            for (int i = 0; i < 4; ++i)
                LDMATRIX_X4(af[i][0], af[i][1], af[i][2], af[i][3],
                            sA + SWZ(aOffBase + (uint32_t)(i * 16 * 128 + ks * 32)));
            #pragma unroll
            for (int jj = 0; jj < 4; ++jj)
                LDMATRIX_X4(bf[jj][0], bf[jj][1], bf[jj][2], bf[jj][3],
                            sB + SWZ(bOffBase + (uint32_t)(jj * 16 * 128 + ks * 32)));
            #pragma unroll
            for (int i = 0; i < 4; ++i)
                #pragma unroll
                for (int j = 0; j < 8; ++j)
                    MMA_16816(acc[i][j], af[i], bf[j >> 1][(j & 1)], bf[j >> 1][(j & 1) + 2]);
        }
        __syncthreads();       // all warps done reading stage `it`
    }

    // Epilogue: frag (c0,c1)@(r, c..c+1), (c2,c3)@(r+8, c..c+1)
    const int rBase = m0 + wm * 64 + (lane >> 2);
    const int cBase = n0 + wn * 64 + (lane & 3) * 2;
    #pragma unroll
    for (int i = 0; i < 4; ++i) {
        const int r = rBase + i * 16;
        #pragma unroll
        for (int j = 0; j < 8; ++j) {
            const int c = cBase + j * 8;
            if (EPI == 1) {
                *(__half2*)&g_H[(size_t)r * S_CAT + c] =
                    __floats2half2_rn(acc[i][j][0], acc[i][j][1]);
                *(__half2*)&g_H[(size_t)(r + 8) * S_CAT + c] =
                    __floats2half2_rn(acc[i][j][2], acc[i][j][3]);
            } else {
                const float b0 = bias[c], b1 = bias[c + 1];
                float2 v0 = make_float2(acc[i][j][0] + b0, acc[i][j][1] + b1);
                float2 v1 = make_float2(acc[i][j][2] + b0, acc[i][j][3] + b1);
                *(float2*)&out[(size_t)r * DOUT + c] = v0;
                *(float2*)&out[(size_t)(r + 8) * DOUT + c] = v1;
            }
        }
    }
}

// ---------------------------------------------------------------------------
// Launch
// ---------------------------------------------------------------------------
extern "C" void kernel_launch(void* const* d_in, const int* in_sizes, int n_in,
                              void* d_out, int out_size) {
    const float* x    = (const float*)d_in[0];
    const float* V    = (const float*)d_in[1];
    const float* U    = (const float*)d_in[2];
    const float* v1   = (const float*)d_in[3];
    const float* v2   = (const float*)d_in[4];
    const float* u1   = (const float*)d_in[5];
    const float* u2   = (const float*)d_in[6];
    const float* V_R  = (const float*)d_in[7];
    const float* U_R  = (const float*)d_in[8];
    const float* v1_R = (const float*)d_in[9];
    const float* v2_R = (const float*)d_in[10];
    const float* u1_R = (const float*)d_in[11];
    const float* u2_R = (const float*)d_in[12];
    const float* bias = (const float*)d_in[13];
    float* out = (float*)d_out;

    cudaFuncSetAttribute(gemm_kernel<DIN, 1>,
                         cudaFuncAttributeMaxDynamicSharedMemorySize, SMEM_DYN_BYTES);
    cudaFuncSetAttribute(gemm_kernel<S_CAT, 2>,
                         cudaFuncAttributeMaxDynamicSharedMemorySize, SMEM_DYN_BYTES);

    // Prep
    prep_x_kernel<<<(int)((size_t)N_TOK * DIN / 4 / 256), 256>>>((const float4*)x);
    prep_B1_kernel<<<(S_CAT * DIN) / 256, 256>>>(V, V_R, v2, v2_R, v1, v1_R, u2, u2_R);
    prep_B2_kernel<<<(DOUT * S_CAT) / 256, 256>>>(U, U_R, u1, u1_R);

    // GEMM1: H = fp16(x) @ B1^T   grid (512/256, 8192/128) = (2, 64) = 128 CTAs
    gemm_kernel<DIN, 1><<<dim3(S_CAT / BN, N_TOK / BM), THREADS, SMEM_DYN_BYTES>>>(nullptr, nullptr);

    // GEMM2: y = H @ B2^T + bias  grid (16, 64) = 1024 CTAs
    gemm_kernel<S_CAT, 2><<<dim3(DOUT / BN, N_TOK / BM), THREADS, SMEM_DYN_BYTES>>>(out, bias);
}

// round 5
// speedup vs baseline: 6.0456x; 1.0657x over previous
#include <cuda_runtime.h>
#include <cuda_fp16.h>
#include <cstdint>
#include <cstddef>

// ---------------------------------------------------------------------------
// Problem constants
// ---------------------------------------------------------------------------
#define N_TOK   8192
#define DIN     4096
#define DOUT    4096
#define S_RANK  256
#define S_CAT   512

// GEMM tiling: 128x128 CTA tile, 2 CTAs/SM for latency hiding
#define BM      128
#define BN      128
#define BK      64          // 64 fp16 = 128 bytes per row -> SW128 swizzle
#define STAGES  3
#define THREADS 256
#define STAGE_A_BYTES (BM * 128)              // 16384
#define STAGE_B_BYTES (BN * 128)              // 16384
#define STAGE_BYTES   (STAGE_A_BYTES + STAGE_B_BYTES)       // 32768
#define SMEM_DYN_BYTES (STAGES * STAGE_BYTES)               // 98304 -> 2 CTAs = 196KB/SM

// ---------------------------------------------------------------------------
// Scratch (device globals; no runtime allocation)
// ---------------------------------------------------------------------------
__device__ __half g_xh[(size_t)N_TOK * DIN];     // fp16(x)                64 MB
__device__ __half g_B1[(size_t)S_CAT * DIN];     // sign(V)*v2*v1*u2        4 MB
__device__ __half g_B2[(size_t)DOUT * S_CAT];    // sign(U)*u1              4 MB
__device__ __half g_H [(size_t)N_TOK * S_CAT];   // H fp16                  8 MB

// ---------------------------------------------------------------------------
// Helpers
// ---------------------------------------------------------------------------
__device__ __forceinline__ uint32_t smem_u32(const void* p) {
    uint32_t a;
    asm("{ .reg .u64 t; cvta.to.shared.u64 t, %1; cvt.u32.u64 %0, t; }" : "=r"(a) : "l"(p));
    return a;
}

#define SWZ(o) ((o) ^ (((o) >> 3) & 0x70))

#define CP_ASYNC16(s, g) \
    asm volatile("cp.async.cg.shared.global [%0], [%1], 16;" :: "r"(s), "l"(g))
#define CP_COMMIT() asm volatile("cp.async.commit_group;")
#define CP_WAIT(n)  asm volatile("cp.async.wait_group %0;" :: "n"(n) : "memory")

#define LDMATRIX_X4(r0, r1, r2, r3, addr)                                     \
    asm volatile("ldmatrix.sync.aligned.m8n8.x4.shared.b16 {%0,%1,%2,%3}, [%4];" \
        : "=r"(r0), "=r"(r1), "=r"(r2), "=r"(r3) : "r"(addr))

#define MMA_16816(d, a, b0, b1)                                               \
    asm volatile("mma.sync.aligned.m16n8k16.row.col.f32.f16.f16.f32 "         \
        "{%0,%1,%2,%3}, {%4,%5,%6,%7}, {%8,%9}, {%0,%1,%2,%3};"               \
        : "+f"((d)[0]), "+f"((d)[1]), "+f"((d)[2]), "+f"((d)[3])              \
        : "r"((a)[0]), "r"((a)[1]), "r"((a)[2]), "r"((a)[3]), "r"(b0), "r"(b1))

__device__ __forceinline__ float sgn(float v) {
    return (v > 0.0f) ? 1.0f : ((v < 0.0f) ? -1.0f : 0.0f);
}

// ---------------------------------------------------------------------------
// Prep kernels
// ---------------------------------------------------------------------------
__global__ void prep_x_kernel(const float4* __restrict__ x) {
    size_t i = (size_t)blockIdx.x * blockDim.x + threadIdx.x;   // 8388608 float4
    float4 v = x[i];
    __half2* o = (__half2*)&g_xh[4 * i];
    o[0] = __floats2half2_rn(v.x, v.y);
    o[1] = __floats2half2_rn(v.z, v.w);
}

// B1[s][i] = sign(Vcat[s][i]) * v2cat[i] * v1cat[s] * u2cat[s]   (all scales folded)
__global__ void prep_B1_kernel(const float* __restrict__ V,   const float* __restrict__ VR,
                               const float* __restrict__ v2,  const float* __restrict__ v2R,
                               const float* __restrict__ v1,  const float* __restrict__ v1R,
                               const float* __restrict__ u2,  const float* __restrict__ u2R) {
    int idx = blockIdx.x * blockDim.x + threadIdx.x;   // S_CAT*DIN
    int s = idx >> 12;
    int i = idx & 4095;
    float val;
    if (s < S_RANK) val = sgn(V [(size_t)s * DIN + i]) * v2[i] * v1[s] * u2[s];
    else {
        int s2 = s - S_RANK;
        val = sgn(VR[(size_t)s2 * DIN + i]) * v2R[i] * v1R[s2] * u2R[s2];
    }
    g_B1[idx] = __float2half(val);
}

__global__ void prep_B2_kernel(const float* __restrict__ U,  const float* __restrict__ UR,
                               const float* __restrict__ u1, const float* __restrict__ u1R) {
    int idx = blockIdx.x * blockDim.x + threadIdx.x;   // DOUT*S_CAT
    int j = idx >> 9;
    int s = idx & 511;
    float val;
    if (s < S_RANK) val = sgn(U [(size_t)j * S_RANK + s]) * u1[j];
    else            val = sgn(UR[(size_t)j * S_RANK + (s - S_RANK)]) * u1R[j];
    g_B2[idx] = __float2half(val);
}

// ---------------------------------------------------------------------------
// Tile loader: stage `it` -> buffer it%STAGES (A: BM rows, B: BN rows, 128B each)
// ---------------------------------------------------------------------------
template <int K>
__device__ __forceinline__ void load_stage(const __half* __restrict__ A,
                                           const __half* __restrict__ B,
                                           uint32_t sm_tiles, int it, int m0, int n0, int tid) {
    const uint32_t sbase = sm_tiles + (it % STAGES) * STAGE_BYTES;
    const int k0 = it * BK;
    #pragma unroll
    for (int u = 0; u < 8; ++u) {
        int q = tid + u * THREADS;            // 0..2047
        if (q < 1024) {                       // A: 128 rows x 8 16B-chunks
            int row = q >> 3, c = q & 7;
            const __half* g = A + (size_t)(m0 + row) * K + k0 + c * 8;
            CP_ASYNC16(sbase + SWZ((uint32_t)(row * 128 + c * 16)), g);
        } else {                              // B: 128 rows x 8 chunks
            int qb = q - 1024;
            int row = qb >> 3, c = qb & 7;
            const __half* g = B + (size_t)(n0 + row) * K + k0 + c * 8;
            CP_ASYNC16(sbase + STAGE_A_BYTES + SWZ((uint32_t)(row * 128 + c * 16)), g);
        }
    }
}

// ---------------------------------------------------------------------------
// HMMA GEMM: C[M,N] = A[M,K] @ B[N,K]^T   (fp16 in, fp32 accum)
// CTA 128x128, warps 2x4 of 64x32, 2 CTAs/SM.
// EPI==1: store fp16 to g_H.  EPI==2: add bias, store fp32 to out.
// ---------------------------------------------------------------------------
template <int K, int EPI>
__global__ __launch_bounds__(THREADS, 2) void gemm_kernel(float* __restrict__ out,
                                                          const float* __restrict__ bias) {
    extern __shared__ char smem_raw[];
    const uint32_t sm_tiles = smem_u32(smem_raw);
    const int tid  = threadIdx.x;
    const int wid  = tid >> 5;
    const int lane = tid & 31;
    const int m0 = blockIdx.y * BM;
    const int n0 = blockIdx.x * BN;
    constexpr int NIT = K / BK;

    const __half* A = (EPI == 1) ? g_xh : g_H;
    const __half* B = (EPI == 1) ? g_B1 : g_B2;

    // Warp grid: 2 (M) x 4 (N); warp tile 64x32
    const int wm = wid >> 2;
    const int wn = wid & 3;

    // ldmatrix per-lane addressing
    const int ldRow = lane & 15;         // row within 16-row block
    const int ldSel = lane >> 4;         // 0/1 -> +16 bytes
    const uint32_t aOffBase = (uint32_t)((wm * 64 + ldRow) * 128 + ldSel * 16);
    const uint32_t bOffBase = (uint32_t)((wn * 32 + ldRow) * 128 + ldSel * 16);

    float acc[4][4][4] = {};   // [m16 tile][n8 tile][frag] = 64 regs

    // Prologue
    #pragma unroll
    for (int s = 0; s < STAGES - 1; ++s) {
        load_stage<K>(A, B, sm_tiles, s, m0, n0, tid);
        CP_COMMIT();
    }

    #pragma unroll 1
    for (int it = 0; it < NIT; ++it) {
        CP_WAIT(STAGES - 2);
        __syncthreads();       // stage `it` fully resident; prior MMAs done

        // Prefetch stage it+2 NOW (overlaps with MMA below).
        if (it + STAGES - 1 < NIT)
            load_stage<K>(A, B, sm_tiles, it + STAGES - 1, m0, n0, tid);
        CP_COMMIT();

        const uint32_t sA = sm_tiles + (it % STAGES) * STAGE_BYTES;
        const uint32_t sB = sA + STAGE_A_BYTES;

        #pragma unroll
        for (int ks = 0; ks < BK / 16; ++ks) {
            uint32_t af[4][4], bf[2][4];
            #pragma unroll
            for (int i = 0; i < 4; ++i)
                LDMATRIX_X4(af[i][0], af[i][1], af[i][2], af[i][3],
                            sA + SWZ(aOffBase + (uint32_t)(i * 16 * 128 + ks * 32)));
            #pragma unroll
            for (int jj = 0; jj < 2; ++jj)
                LDMATRIX_X4(bf[jj][0], bf[jj][1], bf[jj][2], bf[jj][3],
                            sB + SWZ(bOffBase + (uint32_t)(jj * 16 * 128 + ks * 32)));
            #pragma unroll
            for (int i = 0; i < 4; ++i)
                #pragma unroll
                for (int j = 0; j < 4; ++j)
                    MMA_16816(acc[i][j], af[i], bf[j >> 1][(j & 1)], bf[j >> 1][(j & 1) + 2]);
        }
        __syncthreads();       // all warps done reading stage `it`
    }

    // Epilogue: frag (c0,c1)@(r, c..c+1), (c2,c3)@(r+8, c..c+1)
    const int rBase = m0 + wm * 64 + (lane >> 2);
    const int cBase = n0 + wn * 32 + (lane & 3) * 2;
    #pragma unroll
    for (int i = 0; i < 4; ++i) {
        const int r = rBase + i * 16;
        #pragma unroll
        for (int j = 0; j < 4; ++j) {
            const int c = cBase + j * 8;
            if (EPI == 1) {
                *(__half2*)&g_H[(size_t)r * S_CAT + c] =
                    __floats2half2_rn(acc[i][j][0], acc[i][j][1]);
                *(__half2*)&g_H[(size_t)(r + 8) * S_CAT + c] =
                    __floats2half2_rn(acc[i][j][2], acc[i][j][3]);
            } else {
                const float b0 = bias[c], b1 = bias[c + 1];
                float2 v0 = make_float2(acc[i][j][0] + b0, acc[i][j][1] + b1);
                float2 v1 = make_float2(acc[i][j][2] + b0, acc[i][j][3] + b1);
                *(float2*)&out[(size_t)r * DOUT + c] = v0;
                *(float2*)&out[(size_t)(r + 8) * DOUT + c] = v1;
            }
        }
    }
}

// ---------------------------------------------------------------------------
// Launch
// ---------------------------------------------------------------------------
extern "C" void kernel_launch(void* const* d_in, const int* in_sizes, int n_in,
                              void* d_out, int out_size) {
    const float* x    = (const float*)d_in[0];
    const float* V    = (const float*)d_in[1];
    const float* U    = (const float*)d_in[2];
    const float* v1   = (const float*)d_in[3];
    const float* v2   = (const float*)d_in[4];
    const float* u1   = (const float*)d_in[5];
    const float* u2   = (const float*)d_in[6];
    const float* V_R  = (const float*)d_in[7];
    const float* U_R  = (const float*)d_in[8];
    const float* v1_R = (const float*)d_in[9];
    const float* v2_R = (const float*)d_in[10];
    const float* u1_R = (const float*)d_in[11];
    const float* u2_R = (const float*)d_in[12];
    const float* bias = (const float*)d_in[13];
    float* out = (float*)d_out;

    cudaFuncSetAttribute(gemm_kernel<DIN, 1>,
                         cudaFuncAttributeMaxDynamicSharedMemorySize, SMEM_DYN_BYTES);
    cudaFuncSetAttribute(gemm_kernel<S_CAT, 2>,
                         cudaFuncAttributeMaxDynamicSharedMemorySize, SMEM_DYN_BYTES);

    // Prep
    prep_x_kernel<<<(int)((size_t)N_TOK * DIN / 4 / 256), 256>>>((const float4*)x);
    prep_B1_kernel<<<(S_CAT * DIN) / 256, 256>>>(V, V_R, v2, v2_R, v1, v1_R, u2, u2_R);
    prep_B2_kernel<<<(DOUT * S_CAT) / 256, 256>>>(U, U_R, u1, u1_R);

    // GEMM1: H = fp16(x) @ B1^T   grid (512/128, 8192/128) = (4, 64) = 256 CTAs
    gemm_kernel<DIN, 1><<<dim3(S_CAT / BN, N_TOK / BM), THREADS, SMEM_DYN_BYTES>>>(nullptr, nullptr);

    // GEMM2: y = H @ B2^T + bias  grid (32, 64) = 2048 CTAs
    gemm_kernel<S_CAT, 2><<<dim3(DOUT / BN, N_TOK / BM), THREADS, SMEM_DYN_BYTES>>>(out, bias);
}